// round 17
// baseline (speedup 1.0000x reference)
#include <cuda_runtime.h>
#include <math.h>

#define Bn 8
#define Hh 640
#define Ww 640
#define HW (Hh*Ww)          // 409600
#define HW4 (HW/4)          // 102400
#define NCH 10
#define NKER 5
#define NL 16
#define NEGINF (-1e30f)

// ---------------- scratch ----------------
struct Scal {
    int   doneCtr;
    int   negcount[Bn];
    int   npos[Bn];
    float posSum[Bn], posSum2[Bn], totNegQ[Bn], lvSum[Bn];
    float kInter[Bn*NKER], kU1[Bn*NKER], kU2[Bn*NKER];
    float embCnt[Bn][NL];
    float embSum[Bn][NL][4];
};
#define SCAL_WORDS (sizeof(Scal)/4)
__device__ Scal gS;
__device__ unsigned g_negbits[Bn*HW];
__device__ unsigned g_hC[4096];     // rare-path radix hist (global; zeroed on demand)
__device__ float    g_hQ[4096];

__device__ __forceinline__ float sigm(float x){ return 1.0f/(1.0f+expf(-x)); }

// ------- fused dilate (sigmoid-of-max) + OHEM stats + staged compaction ----
// grid (20,20,Bn), block (32,8). Tile 32x32, halo 4.
__global__ void k_dilstats(const float* __restrict__ pred,
                           const float* __restrict__ gt,
                           const float* __restrict__ tm){
    __shared__ float sIn[40][41];
    __shared__ float sHm[40][33];
    __shared__ unsigned sNeg[1024];
    __shared__ int sCnt, sBase;
    __shared__ float sR0[8], sR1[8], sR2[8], sR3[8];
    int b = blockIdx.z;
    int gx0 = blockIdx.x*32 - 4, gy0 = blockIdx.y*32 - 4;
    int tid = threadIdx.y*32 + threadIdx.x;
    int lane = tid & 31, wid = tid >> 5;
    const float* p0 = pred + b*NCH*HW;

    if (tid == 0) sCnt = 0;
    for (int idx = tid; idx < 1600; idx += 256){
        int r = idx/40, c = idx - 40*r;
        int gy = gy0 + r, gx = gx0 + c;
        sIn[r][c] = (gy>=0 && gy<Hh && gx>=0 && gx<Ww) ? p0[gy*Ww + gx] : NEGINF;
    }
    __syncthreads();
    for (int idx = tid; idx < 1280; idx += 256){
        int r = idx >> 5, c = idx & 31;
        float m = sIn[r][c];
        #pragma unroll
        for (int j=1;j<9;j++) m = fmaxf(m, sIn[r][c+j]);
        sHm[r][c] = m;
    }
    __syncthreads();

    int pc = 0; float ps = 0.f, ps2 = 0.f, qn = 0.f;
    #pragma unroll
    for (int k=0;k<4;k++){
        int r = threadIdx.y*4 + k;
        int c = threadIdx.x;
        float m = sHm[r][c];
        #pragma unroll
        for (int j=1;j<9;j++) m = fmaxf(m, sHm[r+j][c]);
        float v = sigm(m);                  // sigmoid after max (monotone)
        int gy = gy0 + 4 + r, gx = gx0 + 4 + c;
        int gi = b*HW + gy*Ww + gx;
        float g  = gt[gi];
        float mm = tm[gi];
        bool isPos = (g > 0.5f) && (mm > 0.5f);
        bool isNeg = (g <= 0.5f) && (mm > 0.5f);
        if (isPos){ pc++; ps += v; ps2 += v*v; }
        if (isNeg) qn += v*v;
        unsigned ball = __ballot_sync(0xffffffffu, isNeg);
        if (isNeg){
            int rank = __popc(ball & ((1u<<lane)-1u));
            int leader = __ffs(ball)-1;
            int base = 0;
            if (lane == leader) base = atomicAdd(&sCnt, __popc(ball));
            base = __shfl_sync(ball, base, leader);
            sNeg[base + rank] = __float_as_uint(v);
        }
    }
    #pragma unroll
    for (int o=16;o;o>>=1){
        pc  += __shfl_down_sync(0xffffffffu, pc, o);
        ps  += __shfl_down_sync(0xffffffffu, ps, o);
        ps2 += __shfl_down_sync(0xffffffffu, ps2, o);
        qn  += __shfl_down_sync(0xffffffffu, qn, o);
    }
    if (lane == 0){ sR0[wid]=(float)pc; sR1[wid]=ps; sR2[wid]=ps2; sR3[wid]=qn; }
    __syncthreads();
    if (tid == 0){
        float a=0,bb=0,cc=0,dd=0;
        #pragma unroll
        for (int w=0;w<8;w++){ a+=sR0[w]; bb+=sR1[w]; cc+=sR2[w]; dd+=sR3[w]; }
        if (a  != 0.f) atomicAdd(&gS.npos[b], (int)a);
        if (bb != 0.f) atomicAdd(&gS.posSum[b], bb);
        if (cc != 0.f) atomicAdd(&gS.posSum2[b], cc);
        if (dd != 0.f) atomicAdd(&gS.totNegQ[b], dd);
        sBase = atomicAdd(&gS.negcount[b], sCnt);
    }
    __syncthreads();
    int cnt = sCnt, base = sBase;
    unsigned* dst = g_negbits + b*HW + base;
    for (int i = tid; i < cnt; i += 256) dst[i] = sNeg[i];
}

// ------- emb pass 1: REGISTER accumulators + predicated adds ---------------
// grid (37, Bn) x 256
__global__ void __launch_bounds__(256) k_emb1(const float* __restrict__ pred,
                       const int* __restrict__ inst,
                       const float* __restrict__ tm){
    __shared__ float sS[8][80];
    int b = blockIdx.y;
    int t = threadIdx.x;
    int lane = t & 31, wid = t >> 5;
    float cnt[NL], a0[NL], a1[NL], a2[NL], a3[NL];
    #pragma unroll
    for (int l=0;l<NL;l++){ cnt[l]=0.f; a0[l]=0.f; a1[l]=0.f; a2[l]=0.f; a3[l]=0.f; }

    const float4* tm4 = (const float4*)(tm + b*HW);
    const int4*   in4 = (const int4*)(inst + b*HW);
    const float4* e0 = (const float4*)(pred + (b*NCH + 6)*HW);
    const float4* e1 = (const float4*)(pred + (b*NCH + 7)*HW);
    const float4* e2 = (const float4*)(pred + (b*NCH + 8)*HW);
    const float4* e3 = (const float4*)(pred + (b*NCH + 9)*HW);
    int stride = gridDim.x*blockDim.x;
    for (int i = blockIdx.x*blockDim.x + t; i < HW4; i += stride){
        float4 m = tm4[i]; int4 gi = in4[i];
        float4 va = e0[i], vb = e1[i], vc = e2[i], vd = e3[i];
        float mv[4] = {m.x, m.y, m.z, m.w};
        int   lv[4] = {gi.x & 15, gi.y & 15, gi.z & 15, gi.w & 15};
        float av[4] = {va.x, va.y, va.z, va.w};
        float bv[4] = {vb.x, vb.y, vb.z, vb.w};
        float cv[4] = {vc.x, vc.y, vc.z, vc.w};
        float dv[4] = {vd.x, vd.y, vd.z, vd.w};
        #pragma unroll
        for (int comp=0; comp<4; comp++){
            bool on = mv[comp] > 0.5f;
            int lab = lv[comp];
            #pragma unroll
            for (int l=0;l<NL;l++){
                bool hit = on && (lab == l);
                if (hit){
                    cnt[l] += 1.f;
                    a0[l] += av[comp];
                    a1[l] += bv[comp];
                    a2[l] += cv[comp];
                    a3[l] += dv[comp];
                }
            }
        }
    }
    #pragma unroll
    for (int l=0;l<NL;l++){
        float v0=cnt[l], v1=a0[l], v2=a1[l], v3=a2[l], v4=a3[l];
        #pragma unroll
        for (int o=16;o;o>>=1){
            v0 += __shfl_down_sync(0xffffffffu, v0, o);
            v1 += __shfl_down_sync(0xffffffffu, v1, o);
            v2 += __shfl_down_sync(0xffffffffu, v2, o);
            v3 += __shfl_down_sync(0xffffffffu, v3, o);
            v4 += __shfl_down_sync(0xffffffffu, v4, o);
        }
        if (lane == 0){
            sS[wid][l*5+0]=v0; sS[wid][l*5+1]=v1; sS[wid][l*5+2]=v2;
            sS[wid][l*5+3]=v3; sS[wid][l*5+4]=v4;
        }
    }
    __syncthreads();
    if (t < 80){
        float s = 0.f;
        #pragma unroll
        for (int w=0;w<8;w++) s += sS[w][t];
        if (s != 0.f){
            int l = t/5, comp = t - 5*l;
            if (comp == 0) atomicAdd(&gS.embCnt[b][l], s);
            else           atomicAdd(&gS.embSum[b][l][comp-1], s);
        }
    }
}

// ---------------- kernels dice: flat grid, 1 quad/thread -------------------
// grid 3200 x 256
__global__ void __launch_bounds__(256) k_kern(const float* __restrict__ pred,
                       const float* __restrict__ gtk,
                       const float* __restrict__ tm){
    __shared__ float sRed[8][15];
    int b = blockIdx.x / 400;
    int i = (blockIdx.x - b*400)*256 + threadIdx.x;
    float4 m = ((const float4*)(tm + b*HW))[i];
    const float* pb = pred + (b*NCH + 1)*HW;
    const float* gb = gtk  + b*NKER*HW;
    float si[5], s1[5], s2[5];
    #pragma unroll
    for (int kc=0;kc<5;kc++){
        float4 p = ((const float4*)(pb + kc*HW))[i];
        float4 g = ((const float4*)(gb + kc*HW))[i];
        float a=0.f,u=0.f,c=0.f;
        if (m.x > 0.5f){ float pp = sigm(p.x); a+=pp*g.x; u+=pp*pp; c+=g.x; }
        if (m.y > 0.5f){ float pp = sigm(p.y); a+=pp*g.y; u+=pp*pp; c+=g.y; }
        if (m.z > 0.5f){ float pp = sigm(p.z); a+=pp*g.z; u+=pp*pp; c+=g.z; }
        if (m.w > 0.5f){ float pp = sigm(p.w); a+=pp*g.w; u+=pp*pp; c+=g.w; }
        si[kc]=a; s1[kc]=u; s2[kc]=c;
    }
    int lane = threadIdx.x & 31, wid = threadIdx.x >> 5;
    #pragma unroll
    for (int kc=0;kc<5;kc++){
        float a = si[kc], u = s1[kc], c = s2[kc];
        #pragma unroll
        for (int o=16;o;o>>=1){
            a += __shfl_down_sync(0xffffffffu, a, o);
            u += __shfl_down_sync(0xffffffffu, u, o);
            c += __shfl_down_sync(0xffffffffu, c, o);
        }
        if (lane == 0){ sRed[wid][kc*3]=a; sRed[wid][kc*3+1]=u; sRed[wid][kc*3+2]=c; }
    }
    __syncthreads();
    if (threadIdx.x < 15){
        float s = 0.f;
        #pragma unroll
        for (int w=0;w<8;w++) s += sRed[w][threadIdx.x];
        int kc = threadIdx.x/3, comp = threadIdx.x - 3*kc;
        if (s != 0.f){
            if (comp==0) atomicAdd(&gS.kInter[b*NKER+kc], s);
            else if (comp==1) atomicAdd(&gS.kU1[b*NKER+kc], s);
            else atomicAdd(&gS.kU2[b*NKER+kc], s);
        }
    }
}

// ------- emb pass 2 + fenced-ticket FINAL assembly in last block -----------
// grid 3200 x 256 ; must be the LAST kernel in the dependency graph
__global__ void __launch_bounds__(256, 4) k_emb2fin(const float* __restrict__ pred,
                       const int* __restrict__ inst,
                       const float* __restrict__ tm,
                       float* __restrict__ out){
    __shared__ float sM[NL][4];
    __shared__ float sInv[NL];
    __shared__ float sRed[8];
    int b = blockIdx.x / 400;
    int i = (blockIdx.x - b*400)*256 + threadIdx.x;
    int t = threadIdx.x;
    if (t < NL){
        int l = t;
        float c = gS.embCnt[b][l];
        float inv = 1.f / fmaxf(c, 1.f);
        sInv[l] = inv;
        #pragma unroll
        for (int d=0;d<4;d++) sM[l][d] = gS.embSum[b][l][d]*inv;
    }
    __syncthreads();
    {
        float4 m = ((const float4*)(tm + b*HW))[i];
        int4 gi  = ((const int4*)(inst + b*HW))[i];
        float4 a = ((const float4*)(pred + (b*NCH + 6)*HW))[i];
        float4 bb= ((const float4*)(pred + (b*NCH + 7)*HW))[i];
        float4 c = ((const float4*)(pred + (b*NCH + 8)*HW))[i];
        float4 d = ((const float4*)(pred + (b*NCH + 9)*HW))[i];
        float acc = 0.f;
        float mv[4] = {m.x, m.y, m.z, m.w};
        int   lv[4] = {gi.x & 15, gi.y & 15, gi.z & 15, gi.w & 15};
        float av[4] = {a.x, a.y, a.z, a.w};
        float bv[4] = {bb.x, bb.y, bb.z, bb.w};
        float cv[4] = {c.x, c.y, c.z, c.w};
        float dv[4] = {d.x, d.y, d.z, d.w};
        #pragma unroll
        for (int comp=0; comp<4; comp++){
            if (mv[comp] > 0.5f){
                int l = lv[comp];
                float v0 = av[comp] - sM[l][0];
                float v1 = bv[comp] - sM[l][1];
                float v2 = cv[comp] - sM[l][2];
                float v3 = dv[comp] - sM[l][3];
                float dd = sqrtf(v0*v0+v1*v1+v2*v2+v3*v3 + 1e-12f);
                float h = dd - 0.5f;
                if (h > 0.f) acc += h*h*sInv[l];
            }
        }
        int lane = t & 31, wid = t >> 5;
        #pragma unroll
        for (int o=16;o;o>>=1) acc += __shfl_down_sync(0xffffffffu, acc, o);
        if (lane == 0) sRed[wid] = acc;
        __syncthreads();
        if (t == 0){
            float s = 0.f;
            #pragma unroll
            for (int w=0;w<8;w++) s += sRed[w];
            if (s != 0.f) atomicAdd(&gS.lvSum[b], s);
        }
    }

    // ---- fenced ticket: last block performs final assembly ----
    __shared__ int sLast;
    __threadfence();
    if (t == 0){
        int ticket = atomicAdd(&gS.doneCtr, 1);
        sLast = (ticket == (int)gridDim.x - 1);
    }
    __syncthreads();
    if (!sLast) return;

    // ======== FINAL ASSEMBLY (one block, 256 threads) ========
    __shared__ Scal sG;
    __shared__ float sNegselArr[Bn];
    __shared__ int   sRare[Bn];
    __shared__ int   sAnyRare;
    __shared__ unsigned sPrefix;
    __shared__ int   sK;
    __shared__ float sAcc;
    __shared__ unsigned scC[256];
    __shared__ float    scQ[256];
    __shared__ float sMean[Bn][NL][4];
    __shared__ float sPres[Bn][NL];
    __shared__ float sN[Bn];
    __shared__ float sLd[Bn];
    __shared__ float sLr[Bn];
    __shared__ float sLossT, sLossK, sLvT, sLdT, sLrT;

    for (int j = t; j < (int)SCAL_WORDS; j += 256)
        ((unsigned*)&sG)[j] = ((const volatile unsigned*)&gS)[j];
    if (t == 0){ sAnyRare = 0; sLossT=0.f; sLossK=0.f; sLvT=0.f; sLdT=0.f; sLrT=0.f; }
    __syncthreads();

    if (t < Bn){
        int bb2 = t;
        int cnt = sG.negcount[bb2];
        int k0 = 3*sG.npos[bb2]; if (k0 > cnt) k0 = cnt;
        int rare = 0;
        if (k0 >= cnt) sNegselArr[bb2] = sG.totNegQ[bb2];
        else if (k0 <= 0) sNegselArr[bb2] = 0.f;
        else { rare = 1; atomicExch(&sAnyRare, 1); }
        sRare[bb2] = rare;
    }
    __syncthreads();
    if (sAnyRare){
        for (int bb2=0; bb2<Bn; bb2++){
            if (!sRare[bb2]) continue;
            int cnt = sG.negcount[bb2];
            int k0 = 3*sG.npos[bb2]; if (k0 > cnt) k0 = cnt;
            if (t == 0){ sK = k0; sAcc = 0.f; sPrefix = 0u; }
            __syncthreads();
            const unsigned* nb = g_negbits + bb2*HW;
            for (int level = 1; level <= 3; level++){
                int K = sK;
                unsigned pfx = sPrefix;
                for (int j=t;j<4096;j+=256){ g_hC[j]=0u; g_hQ[j]=0.f; }
                __syncthreads();
                for (int j = t; j < cnt; j += 256){
                    unsigned bits = nb[j];
                    unsigned bin = 0; bool ok = false;
                    if (level == 1){ bin = bits >> 20; ok = true; }
                    else if (level == 2){ ok = (bits>>20)==(pfx>>20); bin = (bits>>8)&0xFFFu; }
                    else { ok = (bits>>8)==(pfx>>8); bin = bits & 0xFFu; }
                    if (ok){
                        float v = __uint_as_float(bits);
                        atomicAdd(&g_hC[bin], 1u);
                        atomicAdd(&g_hQ[bin], v*v);
                    }
                }
                __syncthreads();
                int nbins = (level == 3) ? 256 : 4096;
                int per = nbins >> 8; if (per == 0) per = 1;
                int hi = nbins - 1 - t*per;
                unsigned c = 0; float q = 0.f;
                if (hi >= 0){
                    for (int j2=0;j2<per;j2++){ int bx = hi - j2; if (bx >= 0){ c += g_hC[bx]; q += g_hQ[bx]; } }
                }
                scC[t] = c; scQ[t] = q;
                __syncthreads();
                for (int off=1; off<256; off<<=1){
                    unsigned cv = (t >= off) ? scC[t-off] : 0u;
                    float    qv = (t >= off) ? scQ[t-off] : 0.f;
                    __syncthreads();
                    scC[t] += cv; scQ[t] += qv;
                    __syncthreads();
                }
                unsigned incl = scC[t], excl = incl - c;
                if (hi >= 0 && (int)excl < K && K <= (int)incl){
                    unsigned acc = excl;
                    float qacc = scQ[t] - q;
                    int chosen = hi;
                    for (int j2=0;j2<per;j2++){
                        int bx = hi - j2;
                        unsigned cc = g_hC[bx];
                        if (acc + cc >= (unsigned)K){ chosen = bx; break; }
                        acc += cc; qacc += g_hQ[bx];
                    }
                    sK = K - (int)acc;
                    sAcc += qacc;
                    if (level == 1)      sPrefix = ((unsigned)chosen) << 20;
                    else if (level == 2) sPrefix |= ((unsigned)chosen) << 8;
                    else                 sPrefix |= (unsigned)chosen;
                }
                __syncthreads();
            }
            if (t == 0){
                float tv = __uint_as_float(sPrefix);
                sNegselArr[bb2] = sAcc + (float)sK * tv * tv;
            }
            __syncthreads();
        }
    }

    if (t < Bn){ sN[t]=0.f; sLd[t]=0.f; sLr[t]=0.f; }
    __syncthreads();
    if (t < Bn*NL){
        int bb2 = t >> 4, l = t & 15;
        float cc = sG.embCnt[bb2][l];
        float pres = (cc > 0.f) ? 1.f : 0.f;
        sPres[bb2][l] = pres;
        float inv = 1.f/fmaxf(cc,1.f);
        #pragma unroll
        for (int d=0;d<4;d++) sMean[bb2][l][d] = sG.embSum[bb2][l][d]*inv;
        if (pres != 0.f) atomicAdd(&sN[bb2], 1.f);
    }
    __syncthreads();
    if (t < Bn*NL){
        int bb2 = t >> 4, l = t & 15;
        if (sPres[bb2][l] != 0.f){
            float d2=0.f;
            #pragma unroll
            for (int d=0;d<4;d++) d2 += sMean[bb2][l][d]*sMean[bb2][l][d];
            atomicAdd(&sLr[bb2], sqrtf(d2 + 1e-12f));
        }
    }
    for (int p0 = t; p0 < Bn*120; p0 += 256){
        int bb2 = p0 / 120, p = p0 - bb2*120;
        int ii = 0, rem = p;
        #pragma unroll
        for (int k=0;k<15;k++){
            int row = 15 - k;
            if (rem < row){ ii = k; break; }
            rem -= row;
        }
        int jj = ii + 1 + rem;
        if (sPres[bb2][ii] != 0.f && sPres[bb2][jj] != 0.f){
            float d2=0.f;
            #pragma unroll
            for (int d=0;d<4;d++){
                float df = sMean[bb2][ii][d]-sMean[bb2][jj][d];
                d2 += df*df;
            }
            float pd = sqrtf(d2 + 1e-12f);
            float h = fmaxf(3.0f - pd, 0.f);
            if (h > 0.f) atomicAdd(&sLd[bb2], h*h);
        }
    }
    __syncthreads();
    if (t < Bn){
        int bb2 = t;
        float inter = sG.posSum[bb2];
        float uni = sG.posSum2[bb2] + sNegselArr[bb2] + (float)sG.npos[bb2] + 1e-6f;
        atomicAdd(&sLossT, 1.f - 2.f*inter/uni);
    }
    if (t >= 64 && t < 64 + Bn*NKER){
        int r = t - 64;
        float uni = sG.kU1[r] + sG.kU2[r] + 1e-6f;
        atomicAdd(&sLossK, 1.f - 2.f*sG.kInter[r]/uni);
    }
    __syncthreads();
    if (t < Bn){
        int bb2 = t;
        float nf = sN[bb2];
        float act = (nf > 1.f) ? 1.f : 0.f;
        if (act != 0.f){
            atomicAdd(&sLvT, sG.lvSum[bb2] / fmaxf(nf, 1.f));
            atomicAdd(&sLdT, sLd[bb2] / fmaxf(nf*(nf-1.f), 1.f));
            atomicAdd(&sLrT, sLr[bb2] / fmaxf(nf, 1.f));
        }
    }
    __syncthreads();
    if (t != 0) return;
    float loss_text = sLossT / (float)Bn;
    float loss_k = sLossK / (float)(Bn*NKER);
    float loss_emb = 0.25f*(sLvT + sLdT + 0.001f*(sLrT/(float)Bn));
    float loss = loss_k + 0.5f*loss_text + loss_emb;
    out[0]=loss; out[1]=loss_text; out[2]=loss_k; out[3]=loss_emb;
}

// ---- launch: 4 workloads + fused sink -------------------------------------
extern "C" void kernel_launch(void* const* d_in, const int* in_sizes, int n_in,
                              void* d_out, int out_size){
    const float* pred   = (const float*)d_in[0];
    const float* gtText = (const float*)d_in[1];
    const float* gtk    = (const float*)d_in[2];
    const float* tm     = (const float*)d_in[3];
    const int*   inst   = (const int*)d_in[4];
    float* out = (float*)d_out;

    static cudaStream_t s1 = nullptr, s2 = nullptr;
    static cudaEvent_t ev0 = nullptr, ev1 = nullptr, ev2 = nullptr;
    static void* pS = nullptr;
    if (s1 == nullptr){
        cudaStreamCreateWithFlags(&s1, cudaStreamNonBlocking);
        cudaStreamCreateWithFlags(&s2, cudaStreamNonBlocking);
        cudaEventCreateWithFlags(&ev0, cudaEventDisableTiming);
        cudaEventCreateWithFlags(&ev1, cudaEventDisableTiming);
        cudaEventCreateWithFlags(&ev2, cudaEventDisableTiming);
        cudaGetSymbolAddress(&pS, gS);
    }

    cudaMemsetAsync(pS, 0, sizeof(Scal), 0);             // workload 1 (zeroes doneCtr too)
    cudaEventRecord(ev0, 0);

    // chain A (s2): emb1
    cudaStreamWaitEvent(s2, ev0, 0);
    k_emb1<<<dim3(37, Bn), 256, 0, s2>>>(pred, inst, tm);                  // 2
    cudaEventRecord(ev2, s2);

    // chain B (s1): dilstats
    cudaStreamWaitEvent(s1, ev0, 0);
    k_dilstats<<<dim3(20,20,Bn), dim3(32,8), 0, s1>>>(pred, gtText, tm);   // 3
    cudaEventRecord(ev1, s1);

    // chain C (main): kern
    k_kern<<<3200, 256>>>(pred, gtk, tm);                                  // 4

    // sink: emb2 + final (after emb1, dilstats; stream-ordered after kern)
    cudaStreamWaitEvent(0, ev1, 0);
    cudaStreamWaitEvent(0, ev2, 0);
    k_emb2fin<<<3200, 256>>>(pred, inst, tm, out);                         // 5 (captured)
}